// round 14
// baseline (speedup 1.0000x reference)
#include <cuda_runtime.h>

// Problem constants
#define B_   8
#define S_   4096
#define H_   1024
#define D_   64
#define BSROWS (B_ * S_)   // 32768 rows

typedef unsigned long long u64;

// Scratch Q/K/V (device globals — no allocation allowed).
__device__ float4 g_Q[BSROWS * 16];
__device__ float4 g_K[BSROWS * 16];
__device__ float4 g_V[BSROWS * 16];

// XOR swizzle at float4 granularity, keyed on the ROW QUAD (row>>2).
// (Proven in R8: column-direction accesses with rows stepping 4 apart get
// key = tx -> all 8 bank groups hit, crossbar at structural floor.)
__device__ __forceinline__ int sw(int row, int c4) {
    return row * 16 + (c4 ^ ((row >> 2) & 15));
}

// ---- packed f32x2 helpers (FFMA2: 2 FLOPs per issue slot) ----
__device__ __forceinline__ u64 pack2(float x, float y) {
    u64 r; asm("mov.b64 %0, {%1,%2};" : "=l"(r) : "f"(x), "f"(y)); return r;
}
__device__ __forceinline__ float2 unpack2(u64 v) {
    float2 r; asm("mov.b64 {%0,%1}, %2;" : "=f"(r.x), "=f"(r.y) : "l"(v)); return r;
}
__device__ __forceinline__ void fma2(u64& d, u64 a, u64 b) {
    asm("fma.rn.f32x2 %0, %1, %2, %0;" : "+l"(d) : "l"(a), "l"(b));
}
__device__ __forceinline__ void mul2(u64& d, u64 a) {
    asm("mul.rn.f32x2 %0, %0, %1;" : "+l"(d) : "l"(a));
}

// ---------------------------------------------------------------------------
// Kernel 1: QKV projection.  out[r][d] = sum_h x[r][h] * W[h][d] + b[d]
// grid = (BSROWS/128, 3), block = 256.  128x64 tile, 8x4 per thread.
// 1.5 B/MAC smem traffic (was 2.0 with 4x4 tiles).
// ---------------------------------------------------------------------------
__global__ __launch_bounds__(256, 2)
void qkv_kernel(const float4* __restrict__ x,
                const float4* __restrict__ Wq, const float* __restrict__ bq,
                const float4* __restrict__ Wk, const float* __restrict__ bk,
                const float4* __restrict__ Wv, const float* __restrict__ bv)
{
    __shared__ float4 As[128 * 16];  // x tile  [row][k]  (swizzled)  32KB
    __shared__ float4 Bs[64 * 16];   // W tile  [k][d]    (swizzled)  16KB
    const ulonglong2* Bs2 = reinterpret_cast<const ulonglong2*>(Bs);

    const int tid = threadIdx.x;
    const int ty  = tid >> 4;        // 0..15 -> rows ty*8 .. ty*8+7
    const int tx  = tid & 15;        // 0..15 -> f4 col tx (4 floats)
    const int r0  = blockIdx.x * 128;

    const float4* W; const float* bias; float4* out;
    if (blockIdx.y == 0)      { W = Wq; bias = bq; out = g_Q; }
    else if (blockIdx.y == 1) { W = Wk; bias = bk; out = g_K; }
    else                      { W = Wv; bias = bv; out = g_V; }

    u64 acc2[8][2];                  // 8 rows x (cols {0,1},{2,3}) packed
#pragma unroll
    for (int i = 0; i < 8; ++i) { acc2[i][0] = 0ull; acc2[i][1] = 0ull; }

    for (int kt = 0; kt < 16; ++kt) {       // 16 chunks of 64 over H=1024
        __syncthreads();
#pragma unroll
        for (int p = 0; p < 8; ++p) {       // 2048 f4 x-tile
            int idx = tid + p * 256;
            int row = idx >> 4, c4 = idx & 15;
            As[sw(row, c4)] = x[(size_t)(r0 + row) * 256 + kt * 16 + c4];
        }
#pragma unroll
        for (int p = 0; p < 4; ++p) {       // 1024 f4 W-tile
            int idx = tid + p * 256;
            int row = idx >> 4, c4 = idx & 15;
            Bs[sw(row, c4)] = W[(size_t)(kt * 64 + row) * 16 + c4];
        }
        __syncthreads();

#pragma unroll 4
        for (int k4 = 0; k4 < 16; ++k4) {
            float4 a4[8]; ulonglong2 b2[4];
#pragma unroll
            for (int i = 0; i < 8; ++i) a4[i] = As[sw(ty * 8 + i, k4)];
#pragma unroll
            for (int kk = 0; kk < 4; ++kk) b2[kk] = Bs2[sw(k4 * 4 + kk, tx)];
#pragma unroll
            for (int i = 0; i < 8; ++i) {
                u64 p0 = pack2(a4[i].x, a4[i].x);
                fma2(acc2[i][0], p0, b2[0].x); fma2(acc2[i][1], p0, b2[0].y);
                u64 p1 = pack2(a4[i].y, a4[i].y);
                fma2(acc2[i][0], p1, b2[1].x); fma2(acc2[i][1], p1, b2[1].y);
                u64 p2 = pack2(a4[i].z, a4[i].z);
                fma2(acc2[i][0], p2, b2[2].x); fma2(acc2[i][1], p2, b2[2].y);
                u64 p3 = pack2(a4[i].w, a4[i].w);
                fma2(acc2[i][0], p3, b2[3].x); fma2(acc2[i][1], p3, b2[3].y);
            }
        }
    }

    const float4 b4 = ((const float4*)bias)[tx];
#pragma unroll
    for (int i = 0; i < 8; ++i) {
        float2 lo = unpack2(acc2[i][0]), hi = unpack2(acc2[i][1]);
        int row = r0 + ty * 8 + i;
        out[(size_t)row * 16 + tx] =
            make_float4(lo.x + b4.x, lo.y + b4.y, hi.x + b4.z, hi.y + b4.w);
    }
}

// ---------------------------------------------------------------------------
// Kernel 2: causal flash attention, fp32 FFMA2.  Br=128, Bc=64, D=64.
// grid = (S/128, B), block = 256 (16x16; each thread: 8 q-rows x 4 k-cols
// for S, 8 q-rows x 4 d-cols for O).  1 CTA/SM, 96KB dynamic smem.
// ---------------------------------------------------------------------------
__global__ __launch_bounds__(256, 1)
void attn_kernel(float4* __restrict__ out)
{
    extern __shared__ float4 smem[];
    float4* Qs = smem;                       // 128 x 16 f4 = 32KB
    float4* Ks = smem + 128 * 16;            //  64 x 16 f4 = 16KB
    float4* Vs = smem + 128 * 16 + 64 * 16;  //  64 x 16 f4 = 16KB
    float4* Ps = smem + 128 * 16 + 2 * 64 * 16;  // 128 x 16 f4 = 32KB
    const ulonglong2* Q2 = reinterpret_cast<const ulonglong2*>(Qs);
    const ulonglong2* K2 = reinterpret_cast<const ulonglong2*>(Ks);
    const ulonglong2* V2 = reinterpret_cast<const ulonglong2*>(Vs);

    const int tid = threadIdx.x;
    const int ty  = tid >> 4;                // rows ty*8 .. ty*8+7
    const int tx  = tid & 15;                // S cols tx*4..+3 / O f4-col tx
    const int qt  = (int)(gridDim.x - 1) - (int)blockIdx.x;  // heavy first
    const int b   = blockIdx.y;
    const int q0  = qt * 128;
    const size_t base = (size_t)b * S_;

    // Load Q tile once (128 rows)
#pragma unroll
    for (int p = 0; p < 8; ++p) {
        int idx = tid + p * 256;
        int row = idx >> 4, c4 = idx & 15;
        Qs[sw(row, c4)] = g_Q[(base + q0 + row) * 16 + c4];
    }

    u64 o2[8][2];
    float m[8], l[8];
#pragma unroll
    for (int i = 0; i < 8; ++i) {
        m[i] = -1e30f; l[i] = 0.0f; o2[i][0] = 0ull; o2[i][1] = 0ull;
    }
    const float scale = 0.125f;   // 1/sqrt(64)
    const int nt = 2 * qt + 2;    // 64-key tiles covering keys <= q0+127

    for (int t = 0; t < nt; ++t) {
        const int k0 = t * 64;
        __syncthreads();          // prev-iter smem reads complete
#pragma unroll
        for (int p = 0; p < 4; ++p) {
            int idx = tid + p * 256;
            int row = idx >> 4, c4 = idx & 15;
            Ks[sw(row, c4)] = g_K[(base + k0 + row) * 16 + c4];
            Vs[sw(row, c4)] = g_V[(base + k0 + row) * 16 + c4];
        }
        __syncthreads();

        // ---- S = Q K^T : d-packed accumulation, horizontal add at end ----
        u64 acc2[8][4];
#pragma unroll
        for (int i = 0; i < 8; ++i)
#pragma unroll
            for (int j = 0; j < 4; ++j) acc2[i][j] = 0ull;

#pragma unroll 2
        for (int k4 = 0; k4 < 16; ++k4) {
            ulonglong2 a2[8], b2[4];
#pragma unroll
            for (int i = 0; i < 8; ++i) a2[i] = Q2[sw(ty * 8 + i, k4)];
#pragma unroll
            for (int j = 0; j < 4; ++j) b2[j] = K2[sw(tx * 4 + j, k4)];
#pragma unroll
            for (int i = 0; i < 8; ++i)
#pragma unroll
                for (int j = 0; j < 4; ++j) {
                    fma2(acc2[i][j], a2[i].x, b2[j].x);
                    fma2(acc2[i][j], a2[i].y, b2[j].y);
                }
        }

        float s[8][4];
#pragma unroll
        for (int i = 0; i < 8; ++i)
#pragma unroll
            for (int j = 0; j < 4; ++j) {
                float2 f = unpack2(acc2[i][j]);
                s[i][j] = f.x + f.y;
            }

        // ---- causal mask (last two tiles only) ----
        if (t >= 2 * qt) {
            const int koff = (t - 2 * qt) << 6;   // 0 or 64
#pragma unroll
            for (int i = 0; i < 8; ++i)
#pragma unroll
                for (int j = 0; j < 4; ++j)
                    if (koff + tx * 4 + j > ty * 8 + i) s[i][j] = -1e30f;
        }

        // ---- online softmax (scale folded into exp) ----
#pragma unroll
        for (int i = 0; i < 8; ++i) {
            float rm = fmaxf(fmaxf(s[i][0], s[i][1]), fmaxf(s[i][2], s[i][3]));
#pragma unroll
            for (int off = 1; off < 16; off <<= 1)
                rm = fmaxf(rm, __shfl_xor_sync(0xffffffffu, rm, off, 16));
            const float mn = fmaxf(m[i], rm);
            const float alpha = __expf(scale * (m[i] - mn));
            m[i] = mn;
            float rs = 0.0f;
#pragma unroll
            for (int j = 0; j < 4; ++j) {
                s[i][j] = __expf(scale * (s[i][j] - mn));   // s becomes P
                rs += s[i][j];
            }
#pragma unroll
            for (int off = 1; off < 16; off <<= 1)
                rs += __shfl_xor_sync(0xffffffffu, rs, off, 16);
            l[i] = l[i] * alpha + rs;
            const u64 aa = pack2(alpha, alpha);
            mul2(o2[i][0], aa);
            mul2(o2[i][1], aa);
        }

        // ---- store P (own rows, own k-col f4) — no sync needed: Ps is a
        //      dedicated buffer, prior PV reads finished before top sync ----
#pragma unroll
        for (int i = 0; i < 8; ++i)
            Ps[sw(ty * 8 + i, tx)] = make_float4(s[i][0], s[i][1], s[i][2], s[i][3]);
        __syncthreads();          // P complete before PV reads

        // ---- O += P @ V : packed f32x2 with broadcast P ----
#pragma unroll 2
        for (int k4 = 0; k4 < 16; ++k4) {
            float4 p4[8]; ulonglong2 v2[4];
#pragma unroll
            for (int i = 0; i < 8; ++i) p4[i] = Ps[sw(ty * 8 + i, k4)];
#pragma unroll
            for (int kk = 0; kk < 4; ++kk) v2[kk] = V2[sw(k4 * 4 + kk, tx)];
#pragma unroll
            for (int i = 0; i < 8; ++i) {
                u64 p0 = pack2(p4[i].x, p4[i].x);
                fma2(o2[i][0], p0, v2[0].x); fma2(o2[i][1], p0, v2[0].y);
                u64 p1 = pack2(p4[i].y, p4[i].y);
                fma2(o2[i][0], p1, v2[1].x); fma2(o2[i][1], p1, v2[1].y);
                u64 p2 = pack2(p4[i].z, p4[i].z);
                fma2(o2[i][0], p2, v2[2].x); fma2(o2[i][1], p2, v2[2].y);
                u64 p3 = pack2(p4[i].w, p4[i].w);
                fma2(o2[i][0], p3, v2[3].x); fma2(o2[i][1], p3, v2[3].y);
            }
        }
    }

    // ---- epilogue: normalize and store ----
#pragma unroll
    for (int i = 0; i < 8; ++i) {
        const float inv = 1.0f / l[i];
        float2 lo = unpack2(o2[i][0]), hi = unpack2(o2[i][1]);
        const int row = q0 + ty * 8 + i;
        out[(base + row) * 16 + tx] =
            make_float4(lo.x * inv, lo.y * inv, hi.x * inv, hi.y * inv);
    }
}

// ---------------------------------------------------------------------------
// Launch
// ---------------------------------------------------------------------------
#define ATTN_SMEM ((128 * 16 + 2 * 64 * 16 + 128 * 16) * (int)sizeof(float4))

extern "C" void kernel_launch(void* const* d_in, const int* in_sizes, int n_in,
                              void* d_out, int out_size)
{
    (void)in_sizes; (void)n_in; (void)out_size;
    const float4* x  = (const float4*)d_in[0];
    const float4* Wq = (const float4*)d_in[1];
    const float*  bq = (const float*) d_in[2];
    const float4* Wk = (const float4*)d_in[3];
    const float*  bk = (const float*) d_in[4];
    const float4* Wv = (const float4*)d_in[5];
    const float*  bv = (const float*) d_in[6];

    static int attr_done = 0;
    if (!attr_done) {
        cudaFuncSetAttribute(attn_kernel,
                             cudaFuncAttributeMaxDynamicSharedMemorySize,
                             ATTN_SMEM);
        attr_done = 1;
    }

    dim3 g1(BSROWS / 128, 3);
    qkv_kernel<<<g1, 256>>>(x, Wq, bq, Wk, bk, Wv, bv);

    dim3 g2(S_ / 128, B_);
    attn_kernel<<<g2, 256, ATTN_SMEM>>>((float4*)d_out);
}

// round 15
// speedup vs baseline: 1.0017x; 1.0017x over previous
#include <cuda_runtime.h>

// Problem constants
#define B_   8
#define S_   4096
#define H_   1024
#define D_   64
#define BSROWS (B_ * S_)   // 32768 rows

typedef unsigned long long u64;

// Scratch Q/K/V (device globals — no allocation allowed).
__device__ float4 g_Q[BSROWS * 16];
__device__ float4 g_K[BSROWS * 16];
__device__ float4 g_V[BSROWS * 16];

// XOR swizzle at float4 granularity, keyed on the ROW QUAD (row>>2).
// (Proven in R8: column-direction accesses with rows stepping 4 apart get
// key = tx -> all 8 bank groups hit, crossbar at structural floor.)
__device__ __forceinline__ int sw(int row, int c4) {
    return row * 16 + (c4 ^ ((row >> 2) & 15));
}

// ---- packed f32x2 helpers (FFMA2: 2 FLOPs per issue slot) ----
__device__ __forceinline__ u64 pack2(float x, float y) {
    u64 r; asm("mov.b64 %0, {%1,%2};" : "=l"(r) : "f"(x), "f"(y)); return r;
}
__device__ __forceinline__ float2 unpack2(u64 v) {
    float2 r; asm("mov.b64 {%0,%1}, %2;" : "=f"(r.x), "=f"(r.y) : "l"(v)); return r;
}
__device__ __forceinline__ void fma2(u64& d, u64 a, u64 b) {
    asm("fma.rn.f32x2 %0, %1, %2, %0;" : "+l"(d) : "l"(a), "l"(b));
}
__device__ __forceinline__ void mul2(u64& d, u64 a) {
    asm("mul.rn.f32x2 %0, %0, %1;" : "+l"(d) : "l"(a));
}

// ---------------------------------------------------------------------------
// Kernel 1: QKV projection.  out[r][d] = sum_h x[r][h] * W[h][d] + b[d]
// grid = (BSROWS/128, 3), block = 256.  128x64 tile, 8x4 per thread.
// 1.5 B/MAC smem traffic (was 2.0 with 4x4 tiles).
// ---------------------------------------------------------------------------
__global__ __launch_bounds__(256, 2)
void qkv_kernel(const float4* __restrict__ x,
                const float4* __restrict__ Wq, const float* __restrict__ bq,
                const float4* __restrict__ Wk, const float* __restrict__ bk,
                const float4* __restrict__ Wv, const float* __restrict__ bv)
{
    __shared__ float4 As[128 * 16];  // x tile  [row][k]  (swizzled)  32KB
    __shared__ float4 Bs[64 * 16];   // W tile  [k][d]    (swizzled)  16KB
    const ulonglong2* Bs2 = reinterpret_cast<const ulonglong2*>(Bs);

    const int tid = threadIdx.x;
    const int ty  = tid >> 4;        // 0..15 -> rows ty*8 .. ty*8+7
    const int tx  = tid & 15;        // 0..15 -> f4 col tx (4 floats)
    const int r0  = blockIdx.x * 128;

    const float4* W; const float* bias; float4* out;
    if (blockIdx.y == 0)      { W = Wq; bias = bq; out = g_Q; }
    else if (blockIdx.y == 1) { W = Wk; bias = bk; out = g_K; }
    else                      { W = Wv; bias = bv; out = g_V; }

    u64 acc2[8][2];                  // 8 rows x (cols {0,1},{2,3}) packed
#pragma unroll
    for (int i = 0; i < 8; ++i) { acc2[i][0] = 0ull; acc2[i][1] = 0ull; }

    for (int kt = 0; kt < 16; ++kt) {       // 16 chunks of 64 over H=1024
        __syncthreads();
#pragma unroll
        for (int p = 0; p < 8; ++p) {       // 2048 f4 x-tile
            int idx = tid + p * 256;
            int row = idx >> 4, c4 = idx & 15;
            As[sw(row, c4)] = x[(size_t)(r0 + row) * 256 + kt * 16 + c4];
        }
#pragma unroll
        for (int p = 0; p < 4; ++p) {       // 1024 f4 W-tile
            int idx = tid + p * 256;
            int row = idx >> 4, c4 = idx & 15;
            Bs[sw(row, c4)] = W[(size_t)(kt * 64 + row) * 16 + c4];
        }
        __syncthreads();

#pragma unroll 4
        for (int k4 = 0; k4 < 16; ++k4) {
            float4 a4[8]; ulonglong2 b2[4];
#pragma unroll
            for (int i = 0; i < 8; ++i) a4[i] = As[sw(ty * 8 + i, k4)];
#pragma unroll
            for (int kk = 0; kk < 4; ++kk) b2[kk] = Bs2[sw(k4 * 4 + kk, tx)];
#pragma unroll
            for (int i = 0; i < 8; ++i) {
                u64 p0 = pack2(a4[i].x, a4[i].x);
                fma2(acc2[i][0], p0, b2[0].x); fma2(acc2[i][1], p0, b2[0].y);
                u64 p1 = pack2(a4[i].y, a4[i].y);
                fma2(acc2[i][0], p1, b2[1].x); fma2(acc2[i][1], p1, b2[1].y);
                u64 p2 = pack2(a4[i].z, a4[i].z);
                fma2(acc2[i][0], p2, b2[2].x); fma2(acc2[i][1], p2, b2[2].y);
                u64 p3 = pack2(a4[i].w, a4[i].w);
                fma2(acc2[i][0], p3, b2[3].x); fma2(acc2[i][1], p3, b2[3].y);
            }
        }
    }

    const float4 b4 = ((const float4*)bias)[tx];
#pragma unroll
    for (int i = 0; i < 8; ++i) {
        float2 lo = unpack2(acc2[i][0]), hi = unpack2(acc2[i][1]);
        int row = r0 + ty * 8 + i;
        out[(size_t)row * 16 + tx] =
            make_float4(lo.x + b4.x, lo.y + b4.y, hi.x + b4.z, hi.y + b4.w);
    }
}

// ---------------------------------------------------------------------------
// Kernel 2: causal flash attention, fp32 FFMA2.  Br=128, Bc=64, D=64.
// grid = (S/128, B), block = 256 (16x16; each thread: 8 q-rows x 4 k-cols
// for S, 8 q-rows x 4 d-cols for O).  1 CTA/SM, 96KB dynamic smem.
// ---------------------------------------------------------------------------
__global__ __launch_bounds__(256, 1)
void attn_kernel(float4* __restrict__ out)
{
    extern __shared__ float4 smem[];
    float4* Qs = smem;                       // 128 x 16 f4 = 32KB
    float4* Ks = smem + 128 * 16;            //  64 x 16 f4 = 16KB
    float4* Vs = smem + 128 * 16 + 64 * 16;  //  64 x 16 f4 = 16KB
    float4* Ps = smem + 128 * 16 + 2 * 64 * 16;  // 128 x 16 f4 = 32KB
    const ulonglong2* Q2 = reinterpret_cast<const ulonglong2*>(Qs);
    const ulonglong2* K2 = reinterpret_cast<const ulonglong2*>(Ks);
    const ulonglong2* V2 = reinterpret_cast<const ulonglong2*>(Vs);

    const int tid = threadIdx.x;
    const int ty  = tid >> 4;                // rows ty*8 .. ty*8+7
    const int tx  = tid & 15;                // S cols tx*4..+3 / O f4-col tx
    const int qt  = (int)(gridDim.x - 1) - (int)blockIdx.x;  // heavy first
    const int b   = blockIdx.y;
    const int q0  = qt * 128;
    const size_t base = (size_t)b * S_;

    // Load Q tile once (128 rows)
#pragma unroll
    for (int p = 0; p < 8; ++p) {
        int idx = tid + p * 256;
        int row = idx >> 4, c4 = idx & 15;
        Qs[sw(row, c4)] = g_Q[(base + q0 + row) * 16 + c4];
    }

    u64 o2[8][2];
    float m[8], l[8];
#pragma unroll
    for (int i = 0; i < 8; ++i) {
        m[i] = -1e30f; l[i] = 0.0f; o2[i][0] = 0ull; o2[i][1] = 0ull;
    }
    const float scale = 0.125f;   // 1/sqrt(64)
    const int nt = 2 * qt + 2;    // 64-key tiles covering keys <= q0+127

    for (int t = 0; t < nt; ++t) {
        const int k0 = t * 64;
        __syncthreads();          // prev-iter smem reads complete
#pragma unroll
        for (int p = 0; p < 4; ++p) {
            int idx = tid + p * 256;
            int row = idx >> 4, c4 = idx & 15;
            Ks[sw(row, c4)] = g_K[(base + k0 + row) * 16 + c4];
            Vs[sw(row, c4)] = g_V[(base + k0 + row) * 16 + c4];
        }
        __syncthreads();

        // ---- S = Q K^T : d-packed accumulation, horizontal add at end ----
        u64 acc2[8][4];
#pragma unroll
        for (int i = 0; i < 8; ++i)
#pragma unroll
            for (int j = 0; j < 4; ++j) acc2[i][j] = 0ull;

#pragma unroll 2
        for (int k4 = 0; k4 < 16; ++k4) {
            ulonglong2 a2[8], b2[4];
#pragma unroll
            for (int i = 0; i < 8; ++i) a2[i] = Q2[sw(ty * 8 + i, k4)];
#pragma unroll
            for (int j = 0; j < 4; ++j) b2[j] = K2[sw(tx * 4 + j, k4)];
#pragma unroll
            for (int i = 0; i < 8; ++i)
#pragma unroll
                for (int j = 0; j < 4; ++j) {
                    fma2(acc2[i][j], a2[i].x, b2[j].x);
                    fma2(acc2[i][j], a2[i].y, b2[j].y);
                }
        }

        float s[8][4];
#pragma unroll
        for (int i = 0; i < 8; ++i)
#pragma unroll
            for (int j = 0; j < 4; ++j) {
                float2 f = unpack2(acc2[i][j]);
                s[i][j] = f.x + f.y;
            }

        // ---- causal mask (last two tiles only) ----
        if (t >= 2 * qt) {
            const int koff = (t - 2 * qt) << 6;   // 0 or 64
#pragma unroll
            for (int i = 0; i < 8; ++i)
#pragma unroll
                for (int j = 0; j < 4; ++j)
                    if (koff + tx * 4 + j > ty * 8 + i) s[i][j] = -1e30f;
        }

        // ---- online softmax (scale folded into exp) ----
#pragma unroll
        for (int i = 0; i < 8; ++i) {
            float rm = fmaxf(fmaxf(s[i][0], s[i][1]), fmaxf(s[i][2], s[i][3]));
#pragma unroll
            for (int off = 1; off < 16; off <<= 1)
                rm = fmaxf(rm, __shfl_xor_sync(0xffffffffu, rm, off, 16));
            const float mn = fmaxf(m[i], rm);
            const float alpha = __expf(scale * (m[i] - mn));
            m[i] = mn;
            float rs = 0.0f;
#pragma unroll
            for (int j = 0; j < 4; ++j) {
                s[i][j] = __expf(scale * (s[i][j] - mn));   // s becomes P
                rs += s[i][j];
            }
#pragma unroll
            for (int off = 1; off < 16; off <<= 1)
                rs += __shfl_xor_sync(0xffffffffu, rs, off, 16);
            l[i] = l[i] * alpha + rs;
            const u64 aa = pack2(alpha, alpha);
            mul2(o2[i][0], aa);
            mul2(o2[i][1], aa);
        }

        // ---- store P (own rows, own k-col f4) — no sync needed: Ps is a
        //      dedicated buffer, prior PV reads finished before top sync ----
#pragma unroll
        for (int i = 0; i < 8; ++i)
            Ps[sw(ty * 8 + i, tx)] = make_float4(s[i][0], s[i][1], s[i][2], s[i][3]);
        __syncthreads();          // P complete before PV reads

        // ---- O += P @ V : packed f32x2 with broadcast P ----
#pragma unroll 2
        for (int k4 = 0; k4 < 16; ++k4) {
            float4 p4[8]; ulonglong2 v2[4];
#pragma unroll
            for (int i = 0; i < 8; ++i) p4[i] = Ps[sw(ty * 8 + i, k4)];
#pragma unroll
            for (int kk = 0; kk < 4; ++kk) v2[kk] = V2[sw(k4 * 4 + kk, tx)];
#pragma unroll
            for (int i = 0; i < 8; ++i) {
                u64 p0 = pack2(p4[i].x, p4[i].x);
                fma2(o2[i][0], p0, v2[0].x); fma2(o2[i][1], p0, v2[0].y);
                u64 p1 = pack2(p4[i].y, p4[i].y);
                fma2(o2[i][0], p1, v2[1].x); fma2(o2[i][1], p1, v2[1].y);
                u64 p2 = pack2(p4[i].z, p4[i].z);
                fma2(o2[i][0], p2, v2[2].x); fma2(o2[i][1], p2, v2[2].y);
                u64 p3 = pack2(p4[i].w, p4[i].w);
                fma2(o2[i][0], p3, v2[3].x); fma2(o2[i][1], p3, v2[3].y);
            }
        }
    }

    // ---- epilogue: normalize and store ----
#pragma unroll
    for (int i = 0; i < 8; ++i) {
        const float inv = 1.0f / l[i];
        float2 lo = unpack2(o2[i][0]), hi = unpack2(o2[i][1]);
        const int row = q0 + ty * 8 + i;
        out[(base + row) * 16 + tx] =
            make_float4(lo.x * inv, lo.y * inv, hi.x * inv, hi.y * inv);
    }
}

// ---------------------------------------------------------------------------
// Launch
// ---------------------------------------------------------------------------
#define ATTN_SMEM ((128 * 16 + 2 * 64 * 16 + 128 * 16) * (int)sizeof(float4))

extern "C" void kernel_launch(void* const* d_in, const int* in_sizes, int n_in,
                              void* d_out, int out_size)
{
    (void)in_sizes; (void)n_in; (void)out_size;
    const float4* x  = (const float4*)d_in[0];
    const float4* Wq = (const float4*)d_in[1];
    const float*  bq = (const float*) d_in[2];
    const float4* Wk = (const float4*)d_in[3];
    const float*  bk = (const float*) d_in[4];
    const float4* Wv = (const float4*)d_in[5];
    const float*  bv = (const float*) d_in[6];

    static int attr_done = 0;
    if (!attr_done) {
        cudaFuncSetAttribute(attn_kernel,
                             cudaFuncAttributeMaxDynamicSharedMemorySize,
                             ATTN_SMEM);
        attr_done = 1;
    }

    dim3 g1(BSROWS / 128, 3);
    qkv_kernel<<<g1, 256>>>(x, Wq, bq, Wk, bk, Wv, bv);

    dim3 g2(S_ / 128, B_);
    attn_kernel<<<g2, 256, ATTN_SMEM>>>((float4*)d_out);
}

// round 16
// speedup vs baseline: 1.0020x; 1.0003x over previous
#include <cuda_runtime.h>

// Problem constants
#define B_   8
#define S_   4096
#define H_   1024
#define D_   64
#define BSROWS (B_ * S_)   // 32768 rows

typedef unsigned long long u64;

// Scratch Q/K/V (device globals — no allocation allowed).
__device__ float4 g_Q[BSROWS * 16];
__device__ float4 g_K[BSROWS * 16];
__device__ float4 g_V[BSROWS * 16];

// XOR swizzle at float4 granularity, keyed on the ROW QUAD (row>>2).
// (Proven in R8: column-direction accesses with rows stepping 4 apart get
// key = tx -> all 8 bank groups hit, crossbar at structural floor.)
__device__ __forceinline__ int sw(int row, int c4) {
    return row * 16 + (c4 ^ ((row >> 2) & 15));
}

// ---- packed f32x2 helpers (FFMA2: 2 FLOPs per issue slot) ----
__device__ __forceinline__ u64 pack2(float x, float y) {
    u64 r; asm("mov.b64 %0, {%1,%2};" : "=l"(r) : "f"(x), "f"(y)); return r;
}
__device__ __forceinline__ float2 unpack2(u64 v) {
    float2 r; asm("mov.b64 {%0,%1}, %2;" : "=f"(r.x), "=f"(r.y) : "l"(v)); return r;
}
__device__ __forceinline__ void fma2(u64& d, u64 a, u64 b) {
    asm("fma.rn.f32x2 %0, %1, %2, %0;" : "+l"(d) : "l"(a), "l"(b));
}
__device__ __forceinline__ void mul2(u64& d, u64 a) {
    asm("mul.rn.f32x2 %0, %0, %1;" : "+l"(d) : "l"(a));
}

// ---------------------------------------------------------------------------
// Kernel 1: QKV projection.  out[r][d] = sum_h x[r][h] * W[h][d] + b[d]
// grid = (BSROWS/128, 3), block = 256.  128x64 tile, 8x4 per thread.
// 1.5 B/MAC smem traffic (was 2.0 with 4x4 tiles).
// ---------------------------------------------------------------------------
__global__ __launch_bounds__(256, 2)
void qkv_kernel(const float4* __restrict__ x,
                const float4* __restrict__ Wq, const float* __restrict__ bq,
                const float4* __restrict__ Wk, const float* __restrict__ bk,
                const float4* __restrict__ Wv, const float* __restrict__ bv)
{
    __shared__ float4 As[128 * 16];  // x tile  [row][k]  (swizzled)  32KB
    __shared__ float4 Bs[64 * 16];   // W tile  [k][d]    (swizzled)  16KB
    const ulonglong2* Bs2 = reinterpret_cast<const ulonglong2*>(Bs);

    const int tid = threadIdx.x;
    const int ty  = tid >> 4;        // 0..15 -> rows ty*8 .. ty*8+7
    const int tx  = tid & 15;        // 0..15 -> f4 col tx (4 floats)
    const int r0  = blockIdx.x * 128;

    const float4* W; const float* bias; float4* out;
    if (blockIdx.y == 0)      { W = Wq; bias = bq; out = g_Q; }
    else if (blockIdx.y == 1) { W = Wk; bias = bk; out = g_K; }
    else                      { W = Wv; bias = bv; out = g_V; }

    u64 acc2[8][2];                  // 8 rows x (cols {0,1},{2,3}) packed
#pragma unroll
    for (int i = 0; i < 8; ++i) { acc2[i][0] = 0ull; acc2[i][1] = 0ull; }

    for (int kt = 0; kt < 16; ++kt) {       // 16 chunks of 64 over H=1024
        __syncthreads();
#pragma unroll
        for (int p = 0; p < 8; ++p) {       // 2048 f4 x-tile
            int idx = tid + p * 256;
            int row = idx >> 4, c4 = idx & 15;
            As[sw(row, c4)] = x[(size_t)(r0 + row) * 256 + kt * 16 + c4];
        }
#pragma unroll
        for (int p = 0; p < 4; ++p) {       // 1024 f4 W-tile
            int idx = tid + p * 256;
            int row = idx >> 4, c4 = idx & 15;
            Bs[sw(row, c4)] = W[(size_t)(kt * 64 + row) * 16 + c4];
        }
        __syncthreads();

#pragma unroll 4
        for (int k4 = 0; k4 < 16; ++k4) {
            float4 a4[8]; ulonglong2 b2[4];
#pragma unroll
            for (int i = 0; i < 8; ++i) a4[i] = As[sw(ty * 8 + i, k4)];
#pragma unroll
            for (int kk = 0; kk < 4; ++kk) b2[kk] = Bs2[sw(k4 * 4 + kk, tx)];
#pragma unroll
            for (int i = 0; i < 8; ++i) {
                u64 p0 = pack2(a4[i].x, a4[i].x);
                fma2(acc2[i][0], p0, b2[0].x); fma2(acc2[i][1], p0, b2[0].y);
                u64 p1 = pack2(a4[i].y, a4[i].y);
                fma2(acc2[i][0], p1, b2[1].x); fma2(acc2[i][1], p1, b2[1].y);
                u64 p2 = pack2(a4[i].z, a4[i].z);
                fma2(acc2[i][0], p2, b2[2].x); fma2(acc2[i][1], p2, b2[2].y);
                u64 p3 = pack2(a4[i].w, a4[i].w);
                fma2(acc2[i][0], p3, b2[3].x); fma2(acc2[i][1], p3, b2[3].y);
            }
        }
    }

    const float4 b4 = ((const float4*)bias)[tx];
#pragma unroll
    for (int i = 0; i < 8; ++i) {
        float2 lo = unpack2(acc2[i][0]), hi = unpack2(acc2[i][1]);
        int row = r0 + ty * 8 + i;
        out[(size_t)row * 16 + tx] =
            make_float4(lo.x + b4.x, lo.y + b4.y, hi.x + b4.z, hi.y + b4.w);
    }
}

// ---------------------------------------------------------------------------
// Kernel 2: causal flash attention, fp32 FFMA2.  Br=128, Bc=64, D=64.
// grid = (S/128, B), block = 256 (16x16; each thread: 8 q-rows x 4 k-cols
// for S, 8 q-rows x 4 d-cols for O).  1 CTA/SM, 96KB dynamic smem.
// ---------------------------------------------------------------------------
__global__ __launch_bounds__(256, 1)
void attn_kernel(float4* __restrict__ out)
{
    extern __shared__ float4 smem[];
    float4* Qs = smem;                       // 128 x 16 f4 = 32KB
    float4* Ks = smem + 128 * 16;            //  64 x 16 f4 = 16KB
    float4* Vs = smem + 128 * 16 + 64 * 16;  //  64 x 16 f4 = 16KB
    float4* Ps = smem + 128 * 16 + 2 * 64 * 16;  // 128 x 16 f4 = 32KB
    const ulonglong2* Q2 = reinterpret_cast<const ulonglong2*>(Qs);
    const ulonglong2* K2 = reinterpret_cast<const ulonglong2*>(Ks);
    const ulonglong2* V2 = reinterpret_cast<const ulonglong2*>(Vs);

    const int tid = threadIdx.x;
    const int ty  = tid >> 4;                // rows ty*8 .. ty*8+7
    const int tx  = tid & 15;                // S cols tx*4..+3 / O f4-col tx
    const int qt  = (int)(gridDim.x - 1) - (int)blockIdx.x;  // heavy first
    const int b   = blockIdx.y;
    const int q0  = qt * 128;
    const size_t base = (size_t)b * S_;

    // Load Q tile once (128 rows)
#pragma unroll
    for (int p = 0; p < 8; ++p) {
        int idx = tid + p * 256;
        int row = idx >> 4, c4 = idx & 15;
        Qs[sw(row, c4)] = g_Q[(base + q0 + row) * 16 + c4];
    }

    u64 o2[8][2];
    float m[8], l[8];
#pragma unroll
    for (int i = 0; i < 8; ++i) {
        m[i] = -1e30f; l[i] = 0.0f; o2[i][0] = 0ull; o2[i][1] = 0ull;
    }
    const float scale = 0.125f;   // 1/sqrt(64)
    const int nt = 2 * qt + 2;    // 64-key tiles covering keys <= q0+127

    for (int t = 0; t < nt; ++t) {
        const int k0 = t * 64;
        __syncthreads();          // prev-iter smem reads complete
#pragma unroll
        for (int p = 0; p < 4; ++p) {
            int idx = tid + p * 256;
            int row = idx >> 4, c4 = idx & 15;
            Ks[sw(row, c4)] = g_K[(base + k0 + row) * 16 + c4];
            Vs[sw(row, c4)] = g_V[(base + k0 + row) * 16 + c4];
        }
        __syncthreads();

        // ---- S = Q K^T : d-packed accumulation, horizontal add at end ----
        u64 acc2[8][4];
#pragma unroll
        for (int i = 0; i < 8; ++i)
#pragma unroll
            for (int j = 0; j < 4; ++j) acc2[i][j] = 0ull;

#pragma unroll 2
        for (int k4 = 0; k4 < 16; ++k4) {
            ulonglong2 a2[8], b2[4];
#pragma unroll
            for (int i = 0; i < 8; ++i) a2[i] = Q2[sw(ty * 8 + i, k4)];
#pragma unroll
            for (int j = 0; j < 4; ++j) b2[j] = K2[sw(tx * 4 + j, k4)];
#pragma unroll
            for (int i = 0; i < 8; ++i)
#pragma unroll
                for (int j = 0; j < 4; ++j) {
                    fma2(acc2[i][j], a2[i].x, b2[j].x);
                    fma2(acc2[i][j], a2[i].y, b2[j].y);
                }
        }

        float s[8][4];
#pragma unroll
        for (int i = 0; i < 8; ++i)
#pragma unroll
            for (int j = 0; j < 4; ++j) {
                float2 f = unpack2(acc2[i][j]);
                s[i][j] = f.x + f.y;
            }

        // ---- causal mask (last two tiles only) ----
        if (t >= 2 * qt) {
            const int koff = (t - 2 * qt) << 6;   // 0 or 64
#pragma unroll
            for (int i = 0; i < 8; ++i)
#pragma unroll
                for (int j = 0; j < 4; ++j)
                    if (koff + tx * 4 + j > ty * 8 + i) s[i][j] = -1e30f;
        }

        // ---- online softmax (scale folded into exp) ----
#pragma unroll
        for (int i = 0; i < 8; ++i) {
            float rm = fmaxf(fmaxf(s[i][0], s[i][1]), fmaxf(s[i][2], s[i][3]));
#pragma unroll
            for (int off = 1; off < 16; off <<= 1)
                rm = fmaxf(rm, __shfl_xor_sync(0xffffffffu, rm, off, 16));
            const float mn = fmaxf(m[i], rm);
            const float alpha = __expf(scale * (m[i] - mn));
            m[i] = mn;
            float rs = 0.0f;
#pragma unroll
            for (int j = 0; j < 4; ++j) {
                s[i][j] = __expf(scale * (s[i][j] - mn));   // s becomes P
                rs += s[i][j];
            }
#pragma unroll
            for (int off = 1; off < 16; off <<= 1)
                rs += __shfl_xor_sync(0xffffffffu, rs, off, 16);
            l[i] = l[i] * alpha + rs;
            const u64 aa = pack2(alpha, alpha);
            mul2(o2[i][0], aa);
            mul2(o2[i][1], aa);
        }

        // ---- store P (own rows, own k-col f4) — no sync needed: Ps is a
        //      dedicated buffer, prior PV reads finished before top sync ----
#pragma unroll
        for (int i = 0; i < 8; ++i)
            Ps[sw(ty * 8 + i, tx)] = make_float4(s[i][0], s[i][1], s[i][2], s[i][3]);
        __syncthreads();          // P complete before PV reads

        // ---- O += P @ V : packed f32x2 with broadcast P ----
#pragma unroll 2
        for (int k4 = 0; k4 < 16; ++k4) {
            float4 p4[8]; ulonglong2 v2[4];
#pragma unroll
            for (int i = 0; i < 8; ++i) p4[i] = Ps[sw(ty * 8 + i, k4)];
#pragma unroll
            for (int kk = 0; kk < 4; ++kk) v2[kk] = V2[sw(k4 * 4 + kk, tx)];
#pragma unroll
            for (int i = 0; i < 8; ++i) {
                u64 p0 = pack2(p4[i].x, p4[i].x);
                fma2(o2[i][0], p0, v2[0].x); fma2(o2[i][1], p0, v2[0].y);
                u64 p1 = pack2(p4[i].y, p4[i].y);
                fma2(o2[i][0], p1, v2[1].x); fma2(o2[i][1], p1, v2[1].y);
                u64 p2 = pack2(p4[i].z, p4[i].z);
                fma2(o2[i][0], p2, v2[2].x); fma2(o2[i][1], p2, v2[2].y);
                u64 p3 = pack2(p4[i].w, p4[i].w);
                fma2(o2[i][0], p3, v2[3].x); fma2(o2[i][1], p3, v2[3].y);
            }
        }
    }

    // ---- epilogue: normalize and store ----
#pragma unroll
    for (int i = 0; i < 8; ++i) {
        const float inv = 1.0f / l[i];
        float2 lo = unpack2(o2[i][0]), hi = unpack2(o2[i][1]);
        const int row = q0 + ty * 8 + i;
        out[(base + row) * 16 + tx] =
            make_float4(lo.x * inv, lo.y * inv, hi.x * inv, hi.y * inv);
    }
}

// ---------------------------------------------------------------------------
// Launch
// ---------------------------------------------------------------------------
#define ATTN_SMEM ((128 * 16 + 2 * 64 * 16 + 128 * 16) * (int)sizeof(float4))

extern "C" void kernel_launch(void* const* d_in, const int* in_sizes, int n_in,
                              void* d_out, int out_size)
{
    (void)in_sizes; (void)n_in; (void)out_size;
    const float4* x  = (const float4*)d_in[0];
    const float4* Wq = (const float4*)d_in[1];
    const float*  bq = (const float*) d_in[2];
    const float4* Wk = (const float4*)d_in[3];
    const float*  bk = (const float*) d_in[4];
    const float4* Wv = (const float4*)d_in[5];
    const float*  bv = (const float*) d_in[6];

    static int attr_done = 0;
    if (!attr_done) {
        cudaFuncSetAttribute(attn_kernel,
                             cudaFuncAttributeMaxDynamicSharedMemorySize,
                             ATTN_SMEM);
        attr_done = 1;
    }

    dim3 g1(BSROWS / 128, 3);
    qkv_kernel<<<g1, 256>>>(x, Wq, bq, Wk, bk, Wv, bv);

    dim3 g2(S_ / 128, B_);
    attn_kernel<<<g2, 256, ATTN_SMEM>>>((float4*)d_out);
}